// round 7
// baseline (speedup 1.0000x reference)
#include <cuda_runtime.h>
#include <cuda_bf16.h>
#include <cuda_fp16.h>
#include <cstdint>

#define NB        4096
#define HID       512
#define KEMB      256
#define NG        50
#define NELEM     100
#define NPAIR     (NELEM * NELEM)       // 10000
#define HEADS     8
#define RBF_R     12.0f

// ---------------- device scratch ----------------
__device__ __align__(16) __half         g_PH[(size_t)NPAIR * HID];     // fp16 (emb@W^T + b_in)
__device__ __align__(16) uint4          g_TPa[(size_t)NB * 128];       // values {v1h x4, v2h x4}
__device__ __align__(16) uint4          g_TPb[(size_t)NB * 128];       // slopes {s1h x4, s2h x4} (fp16)
__device__ __align__(16) float          g_WT[KEMB * HID];              // W_in emb part, [k][j]
__device__ __align__(16) float          g_Wr[NG * HID];                // W_in rbf part, [g][j]
__device__ __align__(16) float          g_Wg[NG * HID];                // gate_W,       [g][j]
__device__ __align__(16) float2         g_WP[4 * HID];                 // head-pair interleaved W_out

typedef unsigned long long ull;

__device__ __forceinline__ void fma2(ull& d, ull a, ull b) {
    asm("fma.rn.f32x2 %0, %1, %2, %0;" : "+l"(d) : "l"(a), "l"(b));
}
__device__ __forceinline__ ull pack2(float x, float y) {
    ull r; asm("mov.b64 %0, {%1, %2};" : "=l"(r) : "f"(x), "f"(y)); return r;
}
__device__ __forceinline__ float2 unpack2(ull v) {
    float2 r; asm("mov.b64 {%0, %1}, %2;" : "=f"(r.x), "=f"(r.y) : "l"(v)); return r;
}
__device__ __forceinline__ float rcpa(float x) {
    float r; asm("rcp.approx.ftz.f32 %0, %1;" : "=f"(r) : "f"(x)); return r;
}
__device__ __forceinline__ void cp16(uint32_t sa, const void* g) {
    asm volatile("cp.async.cg.shared.global [%0], [%1], 16;" :: "r"(sa), "l"(g));
}
__device__ __forceinline__ void cp_commit() { asm volatile("cp.async.commit_group;"); }
__device__ __forceinline__ void cp_wait1()  { asm volatile("cp.async.wait_group 1;"); }

// ================= prep 0: transposes + W_out interleave =================
__global__ void prep_transpose(const float* __restrict__ W_in,
                               const float* __restrict__ gate_W,
                               const float* __restrict__ W_out) {
    int idx = blockIdx.x * blockDim.x + threadIdx.x;
    int total = KEMB * HID + NG * HID * 2 + 4 * HID;
    if (idx >= total) return;
    if (idx < KEMB * HID) {
        int k = idx >> 9, j = idx & (HID - 1);
        g_WT[idx] = W_in[j * 306 + k];
    } else if (idx < KEMB * HID + NG * HID) {
        int r = idx - KEMB * HID;
        int g = r >> 9, j = r & (HID - 1);
        g_Wr[r] = W_in[j * 306 + 256 + g];
    } else if (idx < KEMB * HID + 2 * NG * HID) {
        int r = idx - KEMB * HID - NG * HID;
        int g = r >> 9, j = r & (HID - 1);
        g_Wg[r] = gate_W[j * NG + g];
    } else {
        int r = idx - KEMB * HID - 2 * NG * HID;   // [0, 2048)
        int hp = r >> 9, j = r & (HID - 1);
        g_WP[r] = make_float2(W_out[(2 * hp) * HID + j], W_out[(2 * hp + 1) * HID + j]);
    }
}

// ================= prep 1: rbf tables, packed SoA =================
#define TBL_SMEM ((2 * NG * HID + 4 * HID + 128) * 4)
__global__ void __launch_bounds__(512, 1) prep_tables_pack() {
    extern __shared__ float smw[];
    float* Ws1  = smw;
    float* Ws2  = smw + NG * HID;
    float* sv1  = smw + 2 * NG * HID;        // [512]
    float* sv2  = sv1 + HID;
    float* sv1n = sv2 + HID;
    float* sv2n = sv1n + HID;
    float* rbf  = sv2n + HID;                // [64]
    float* rbfn = rbf + 64;                  // [64]
    const int tid = threadIdx.x;
    for (int i = tid; i < NG * HID; i += 512) { Ws1[i] = g_Wr[i]; Ws2[i] = g_Wg[i]; }
    __syncthreads();
    const float delta = RBF_R / 49.0f;
    const float coeff = -0.5f / (delta * delta);
    const float binw  = RBF_R / (float)NB;
    for (int b = blockIdx.x; b < NB; b += gridDim.x) {
        if (tid < NG) {
            float t = (float)b * binw - (float)tid * delta;
            rbf[tid] = __expf(coeff * t * t);
        } else if (tid >= 64 && tid < 64 + NG) {
            float t = (float)(b + 1) * binw - (float)(tid - 64) * delta;
            rbfn[tid - 64] = __expf(coeff * t * t);
        }
        __syncthreads();
        float a1 = 0.f, a2 = 0.f, a1n = 0.f, a2n = 0.f;
#pragma unroll
        for (int g = 0; g < NG; ++g) {
            float r = rbf[g], rn = rbfn[g];
            float w1 = Ws1[g * HID + tid], w2 = Ws2[g * HID + tid];
            a1  = fmaf(r,  w1, a1);   a2  = fmaf(r,  w2, a2);
            a1n = fmaf(rn, w1, a1n);  a2n = fmaf(rn, w2, a2n);
        }
        sv1[tid] = a1; sv2[tid] = a2; sv1n[tid] = a1n; sv2n[tid] = a2n;
        __syncthreads();
        if (tid < 128) {
            int q = tid * 4;
            uint4 A, B;
            __half2 h;
            h = __floats2half2_rn(sv1[q],     sv1[q + 1]); A.x = *(uint32_t*)&h;
            h = __floats2half2_rn(sv1[q + 2], sv1[q + 3]); A.y = *(uint32_t*)&h;
            h = __floats2half2_rn(sv2[q],     sv2[q + 1]); A.z = *(uint32_t*)&h;
            h = __floats2half2_rn(sv2[q + 2], sv2[q + 3]); A.w = *(uint32_t*)&h;
            h = __floats2half2_rn(sv1n[q]     - sv1[q],     sv1n[q + 1] - sv1[q + 1]); B.x = *(uint32_t*)&h;
            h = __floats2half2_rn(sv1n[q + 2] - sv1[q + 2], sv1n[q + 3] - sv1[q + 3]); B.y = *(uint32_t*)&h;
            h = __floats2half2_rn(sv2n[q]     - sv2[q],     sv2n[q + 1] - sv2[q + 1]); B.z = *(uint32_t*)&h;
            h = __floats2half2_rn(sv2n[q + 2] - sv2[q + 2], sv2n[q + 3] - sv2[q + 3]); B.w = *(uint32_t*)&h;
            size_t o = (size_t)b * 128 + tid;
            g_TPa[o] = A;
            g_TPb[o] = B;
        }
        __syncthreads();
    }
}

// ================= prep 2: P = emb @ W_emb^T + b_in (FFMA2 GEMM) =========
#define PP_XSTRIDE 36
__device__ __forceinline__ void fma_block(ull (&acc)[4][4], const float* xr, const float* wr) {
    float4 xv = *(const float4*)xr;
    const ull* wp = (const ull*)wr;
    ull w0 = wp[0], w1 = wp[1], w2 = wp[2], w3 = wp[3];
    ull x0 = pack2(xv.x, xv.x), x1 = pack2(xv.y, xv.y);
    ull x2 = pack2(xv.z, xv.z), x3 = pack2(xv.w, xv.w);
    fma2(acc[0][0], w0, x0); fma2(acc[0][1], w1, x0);
    fma2(acc[0][2], w2, x0); fma2(acc[0][3], w3, x0);
    fma2(acc[1][0], w0, x1); fma2(acc[1][1], w1, x1);
    fma2(acc[1][2], w2, x1); fma2(acc[1][3], w3, x1);
    fma2(acc[2][0], w0, x2); fma2(acc[2][1], w1, x2);
    fma2(acc[2][2], w2, x2); fma2(acc[2][3], w3, x2);
    fma2(acc[3][0], w0, x3); fma2(acc[3][1], w1, x3);
    fma2(acc[3][2], w2, x3); fma2(acc[3][3], w3, x3);
}

#define PP_SMEM_BYTES (42496 * 4)
__global__ void __launch_bounds__(512, 1)
prep_P_kernel(const float* __restrict__ emb_table, const float* __restrict__ b_in) {
    extern __shared__ float sm[];
    float* Xs  = sm;
    float* WsA = sm + 9216;
    float* WsB = sm + 9216 + 16384;
    float* bsS = sm + 9216 + 32768;

    const int tid = threadIdx.x;
    const int p0  = blockIdx.x * 32;
    const int eg = tid & 7, jg = tid >> 3, jbase = jg * 8;
    const float4* emb4 = (const float4*)emb_table;

    for (int i = tid; i < 32 * 64; i += 512) {
        int e = i >> 6, c = i & 63;
        int pair = p0 + e;
        float4 v = (pair < NPAIR) ? emb4[(size_t)pair * 64 + c] : make_float4(0, 0, 0, 0);
        int kb = c * 4;
        Xs[(kb + 0) * PP_XSTRIDE + e] = v.x;
        Xs[(kb + 1) * PP_XSTRIDE + e] = v.y;
        Xs[(kb + 2) * PP_XSTRIDE + e] = v.z;
        Xs[(kb + 3) * PP_XSTRIDE + e] = v.w;
    }
    bsS[tid] = b_in[tid];

    {
        uint32_t sbase;
        asm("{ .reg .u64 t; cvta.to.shared.u64 t, %1; cvt.u32.u64 %0, t; }" : "=r"(sbase) : "l"(WsA));
        const float4* src = (const float4*)g_WT;
        for (int i = tid; i < 4096; i += 512) cp16(sbase + i * 16, src + i);
    }
    cp_commit();

    ull acc[4][4];
#pragma unroll
    for (int a = 0; a < 4; a++)
#pragma unroll
        for (int b = 0; b < 4; b++) acc[a][b] = 0ull;

    for (int t = 0; t < 8; ++t) {
        if (t + 1 < 8) {
            float* dstb = ((t + 1) & 1) ? WsB : WsA;
            uint32_t sbase;
            asm("{ .reg .u64 t; cvta.to.shared.u64 t, %1; cvt.u32.u64 %0, t; }" : "=r"(sbase) : "l"(dstb));
            const float4* src = (const float4*)(g_WT + (t + 1) * 32 * HID);
            for (int i = tid; i < 4096; i += 512) cp16(sbase + i * 16, src + i);
        }
        cp_commit();
        cp_wait1();
        __syncthreads();
        const float* W = (t & 1) ? WsB : WsA;
        const int kb = t * 32;
#pragma unroll
        for (int kk = 0; kk < 32; ++kk)
            fma_block(acc, Xs + (kb + kk) * PP_XSTRIDE + eg * 4, W + kk * HID + jbase);
        __syncthreads();
    }

#pragma unroll
    for (int e4 = 0; e4 < 4; ++e4) {
        int pair = p0 + eg * 4 + e4;
        if (pair < NPAIR) {
#pragma unroll
            for (int jp = 0; jp < 4; ++jp) {
                float2 v = unpack2(acc[e4][jp]);
                int j0 = jbase + jp * 2;
                g_PH[(size_t)pair * HID + j0]     = __float2half(v.x + bsS[j0]);
                g_PH[(size_t)pair * HID + j0 + 1] = __float2half(v.y + bsS[j0 + 1]);
            }
        }
    }
}

// ================= main kernel =================
#define MT          256
#define BEDG        64
#define WPS_F       (4 * HID * 2)             // 4096 floats (float2 [4][512])
#define RB_F        (8 * 32 * 33)             // 8448
#define STG_F       (WPS_F + RB_F)            // 12544
#define MAIN_SMEM_B ((STG_F + 192) * 4)       // 50944 B

__global__ void __launch_bounds__(MT, 3)
pair_main(const int* __restrict__ anum,
          const int* __restrict__ edge_index,
          const int* __restrict__ edge_to_src,
          const float* __restrict__ dist,
          const float* __restrict__ b_out,
          float* __restrict__ out, int E) {
    extern __shared__ float sm[];
    float* Wps   = sm;                  // interleaved head-pair W_out, float2 [4][512]
    float* Rb    = sm + WPS_F;
    int*   spidx = (int*)(sm + STG_F);
    int*   sbin  = (int*)(sm + STG_F + 64);
    float* sfrac = sm + STG_F + 128;

    const int tid  = threadIdx.x;
    const int wid  = tid >> 5;
    const int lane = tid & 31;
    const int e0   = blockIdx.x * BEDG;

    for (int i = tid; i < WPS_F / 4; i += MT)
        ((float4*)Wps)[i] = ((const float4*)g_WP)[i];
    if (tid < BEDG) {
        int e = e0 + tid; if (e >= E) e = E - 1;
        int f = edge_to_src[e];
        int i0 = edge_index[f];
        int i1 = edge_index[E + f];
        spidx[tid] = anum[i0] + NELEM * anum[i1];
        float x = dist[e] * ((float)NB / RBF_R);
        int b = (int)x; if (b > NB - 1) b = NB - 1;
        sbin[tid] = b;
        sfrac[tid] = x - (float)b;
    }
    __syncthreads();

    const uint2* P2 = (const uint2*)g_PH;
    const ull*   Wp2 = (const ull*)Wps;       // float2 == 8B
    float* RbW = Rb + wid * (32 * 33);
    float bo8 = __ldg(&b_out[lane & 7]);

#pragma unroll 1
    for (int grp = 0; grp < 2; ++grp) {
        ull po2[4][4];                 // [edge][head-pair] f32x2 accumulators
#pragma unroll
        for (int a = 0; a < 4; a++)
#pragma unroll
            for (int b = 0; b < 4; b++) po2[a][b] = 0ull;

#pragma unroll 1
        for (int pass = 0; pass < 2; ++pass) {
            int pe[2], be[2]; __half2 fh2[2];
#pragma unroll
            for (int e = 0; e < 2; ++e) {
                int sl = wid * 8 + grp * 4 + pass * 2 + e;
                pe[e] = spidx[sl]; be[e] = sbin[sl];
                fh2[e] = __float2half2_rn(sfrac[sl]);
            }
#pragma unroll
            for (int jq = 0; jq < 4; ++jq) {
                const int off = jq * 32 + lane;
                ull h[2][4];
#pragma unroll
                for (int e = 0; e < 2; ++e) {
                    size_t tr = (size_t)be[e] * 128 + off;
                    uint4 tA = __ldg(g_TPa + tr);
                    uint4 tB = __ldg(g_TPb + tr);
                    uint2 ph = __ldg(P2 + (size_t)pe[e] * 128 + off);
                    __half2 f2 = fh2[e];
                    __half2 t1a = __hfma2(f2, *(const __half2*)&tB.x, *(const __half2*)&tA.x);
                    __half2 t1b = __hfma2(f2, *(const __half2*)&tB.y, *(const __half2*)&tA.y);
                    __half2 g2a = __hfma2(f2, *(const __half2*)&tB.z, *(const __half2*)&tA.z);
                    __half2 g2b = __hfma2(f2, *(const __half2*)&tB.w, *(const __half2*)&tA.w);
                    __half2 pa  = __hadd2(*(const __half2*)&ph.x, t1a);
                    __half2 pb  = __hadd2(*(const __half2*)&ph.y, t1b);
                    float2 p01 = __half22float2(pa);
                    float2 p23 = __half22float2(pb);
                    float2 g01 = __half22float2(g2a);
                    float2 g23 = __half22float2(g2b);
                    float q0 = 1.0f + __expf(-p01.x);
                    float q1 = 1.0f + __expf(-p01.y);
                    float q2 = 1.0f + __expf(-p23.x);
                    float q3 = 1.0f + __expf(-p23.y);
                    float q01 = q0 * q1, q23 = q2 * q3;
                    float rall = rcpa(q01 * q23);
                    float r01 = rall * q23, r23 = rall * q01;
                    float hv0 = p01.x * g01.x * (r01 * q1);
                    float hv1 = p01.y * g01.y * (r01 * q0);
                    float hv2 = p23.x * g23.x * (r23 * q3);
                    float hv3 = p23.y * g23.y * (r23 * q2);
                    h[e][0] = pack2(hv0, hv0); h[e][1] = pack2(hv1, hv1);
                    h[e][2] = pack2(hv2, hv2); h[e][3] = pack2(hv3, hv3);
                }
#pragma unroll
                for (int hp = 0; hp < 4; ++hp) {
                    const ull* wr = Wp2 + hp * HID + jq * 128 + lane * 4;
                    ull w0 = wr[0], w1 = wr[1], w2 = wr[2], w3 = wr[3];
                    int eb = pass * 2;
                    fma2(po2[eb][hp],     w0, h[0][0]);
                    fma2(po2[eb][hp],     w1, h[0][1]);
                    fma2(po2[eb][hp],     w2, h[0][2]);
                    fma2(po2[eb][hp],     w3, h[0][3]);
                    fma2(po2[eb + 1][hp], w0, h[1][0]);
                    fma2(po2[eb + 1][hp], w1, h[1][1]);
                    fma2(po2[eb + 1][hp], w2, h[1][2]);
                    fma2(po2[eb + 1][hp], w3, h[1][3]);
                }
            }
        }

        // per-warp smem reduction (conflict-free, deterministic)
#pragma unroll
        for (int e4 = 0; e4 < 4; ++e4)
#pragma unroll
            for (int hp = 0; hp < 4; ++hp) {
                float2 v = unpack2(po2[e4][hp]);
                RbW[lane * 33 + e4 * 8 + 2 * hp]     = v.x;
                RbW[lane * 33 + e4 * 8 + 2 * hp + 1] = v.y;
            }
        __syncwarp();
        float s = bo8;
#pragma unroll
        for (int l = 0; l < 32; ++l) s += RbW[l * 33 + lane];
        int e4 = lane >> 3, h = lane & 7;
        int ge = e0 + wid * 8 + grp * 4 + e4;
        if (ge < E) out[(size_t)h * E + ge] = s;
        __syncwarp();
    }
}

// ================= launch =================
extern "C" void kernel_launch(void* const* d_in, const int* in_sizes, int n_in,
                              void* d_out, int out_size) {
    const int*   anum        = (const int*)d_in[0];
    const int*   edge_index  = (const int*)d_in[1];
    const int*   edge_to_src = (const int*)d_in[2];
    const float* dist        = (const float*)d_in[3];
    const float* emb_table   = (const float*)d_in[4];
    const float* gate_W      = (const float*)d_in[5];
    const float* W_in        = (const float*)d_in[6];
    const float* b_in        = (const float*)d_in[7];
    const float* W_out       = (const float*)d_in[8];
    const float* b_out       = (const float*)d_in[9];
    float* out = (float*)d_out;
    const int E = in_sizes[2];

    {
        int tot = KEMB * HID + NG * HID * 2 + 4 * HID;
        prep_transpose<<<(tot + 255) / 256, 256>>>(W_in, gate_W, W_out);
    }
    cudaFuncSetAttribute(prep_tables_pack, cudaFuncAttributeMaxDynamicSharedMemorySize, TBL_SMEM);
    prep_tables_pack<<<148, 512, TBL_SMEM>>>();
    cudaFuncSetAttribute(prep_P_kernel, cudaFuncAttributeMaxDynamicSharedMemorySize, PP_SMEM_BYTES);
    prep_P_kernel<<<(NPAIR + 31) / 32, 512, PP_SMEM_BYTES>>>(emb_table, b_in);
    cudaFuncSetAttribute(pair_main, cudaFuncAttributeMaxDynamicSharedMemorySize, MAIN_SMEM_B);
    pair_main<<<(E + BEDG - 1) / BEDG, MT, MAIN_SMEM_B>>>(
        anum, edge_index, edge_to_src, dist, b_out, out, E);
}

// round 8
// speedup vs baseline: 1.4742x; 1.4742x over previous
#include <cuda_runtime.h>
#include <cuda_bf16.h>
#include <cuda_fp16.h>
#include <cstdint>

#define NB        4096
#define HID       512
#define KEMB      256
#define NG        50
#define NELEM     100
#define NPAIR     (NELEM * NELEM)       // 10000
#define HEADS     8
#define RBF_R     12.0f

// ---------------- device scratch ----------------
__device__ __align__(16) __half         g_PH[(size_t)NPAIR * HID];     // fp16 (emb@W^T + b_in)
__device__ __align__(16) uint4          g_TPa[(size_t)NB * 128];       // values {v1h x4, v2h x4}
__device__ __align__(16) uint4          g_TPb[(size_t)NB * 128];       // slopes {s1h x4, s2h x4} (fp16)
__device__ __align__(16) float          g_WT[KEMB * HID];              // W_in emb part, [k][j]
__device__ __align__(16) float          g_Wr[NG * HID];                // W_in rbf part, [g][j]
__device__ __align__(16) float          g_Wg[NG * HID];                // gate_W,       [g][j]
// W_out interleaved: [jq][jpos][hpp][lane] float4 = heads (4hpp..4hpp+3) at j=(jq*32+lane)*4+jpos
__device__ __align__(16) float4         g_WQ[1024];

typedef unsigned long long ull;

__device__ __forceinline__ void fma2(ull& d, ull a, ull b) {
    asm("fma.rn.f32x2 %0, %1, %2, %0;" : "+l"(d) : "l"(a), "l"(b));
}
__device__ __forceinline__ ull pack2(float x, float y) {
    ull r; asm("mov.b64 %0, {%1, %2};" : "=l"(r) : "f"(x), "f"(y)); return r;
}
__device__ __forceinline__ float2 unpack2(ull v) {
    float2 r; asm("mov.b64 {%0, %1}, %2;" : "=f"(r.x), "=f"(r.y) : "l"(v)); return r;
}
__device__ __forceinline__ float rcpa(float x) {
    float r; asm("rcp.approx.ftz.f32 %0, %1;" : "=f"(r) : "f"(x)); return r;
}
__device__ __forceinline__ void cp16(uint32_t sa, const void* g) {
    asm volatile("cp.async.cg.shared.global [%0], [%1], 16;" :: "r"(sa), "l"(g));
}
__device__ __forceinline__ void cp_commit() { asm volatile("cp.async.commit_group;"); }
__device__ __forceinline__ void cp_wait1()  { asm volatile("cp.async.wait_group 1;"); }

// ================= prep 0: transposes + W_out interleave =================
__global__ void prep_transpose(const float* __restrict__ W_in,
                               const float* __restrict__ gate_W,
                               const float* __restrict__ W_out) {
    int idx = blockIdx.x * blockDim.x + threadIdx.x;
    int total = KEMB * HID + NG * HID * 2 + 1024;
    if (idx >= total) return;
    if (idx < KEMB * HID) {
        int k = idx >> 9, j = idx & (HID - 1);
        g_WT[idx] = W_in[j * 306 + k];
    } else if (idx < KEMB * HID + NG * HID) {
        int r = idx - KEMB * HID;
        int g = r >> 9, j = r & (HID - 1);
        g_Wr[r] = W_in[j * 306 + 256 + g];
    } else if (idx < KEMB * HID + 2 * NG * HID) {
        int r = idx - KEMB * HID - NG * HID;
        int g = r >> 9, j = r & (HID - 1);
        g_Wg[r] = gate_W[j * NG + g];
    } else {
        int r = idx - KEMB * HID - 2 * NG * HID;   // [0, 1024)
        int lane = r & 31;
        int hpp  = (r >> 5) & 1;
        int jpos = (r >> 6) & 3;
        int jq   = r >> 8;
        int jj   = (jq * 32 + lane) * 4 + jpos;
        g_WQ[r] = make_float4(W_out[(4 * hpp + 0) * HID + jj],
                              W_out[(4 * hpp + 1) * HID + jj],
                              W_out[(4 * hpp + 2) * HID + jj],
                              W_out[(4 * hpp + 3) * HID + jj]);
    }
}

// ================= prep 1: rbf tables, packed SoA =================
#define TBL_SMEM ((2 * NG * HID + 4 * HID + 128) * 4)
__global__ void __launch_bounds__(512, 1) prep_tables_pack() {
    extern __shared__ float smw[];
    float* Ws1  = smw;
    float* Ws2  = smw + NG * HID;
    float* sv1  = smw + 2 * NG * HID;        // [512]
    float* sv2  = sv1 + HID;
    float* sv1n = sv2 + HID;
    float* sv2n = sv1n + HID;
    float* rbf  = sv2n + HID;                // [64]
    float* rbfn = rbf + 64;                  // [64]
    const int tid = threadIdx.x;
    for (int i = tid; i < NG * HID; i += 512) { Ws1[i] = g_Wr[i]; Ws2[i] = g_Wg[i]; }
    __syncthreads();
    const float delta = RBF_R / 49.0f;
    const float coeff = -0.5f / (delta * delta);
    const float binw  = RBF_R / (float)NB;
    for (int b = blockIdx.x; b < NB; b += gridDim.x) {
        if (tid < NG) {
            float t = (float)b * binw - (float)tid * delta;
            rbf[tid] = __expf(coeff * t * t);
        } else if (tid >= 64 && tid < 64 + NG) {
            float t = (float)(b + 1) * binw - (float)(tid - 64) * delta;
            rbfn[tid - 64] = __expf(coeff * t * t);
        }
        __syncthreads();
        float a1 = 0.f, a2 = 0.f, a1n = 0.f, a2n = 0.f;
#pragma unroll
        for (int g = 0; g < NG; ++g) {
            float r = rbf[g], rn = rbfn[g];
            float w1 = Ws1[g * HID + tid], w2 = Ws2[g * HID + tid];
            a1  = fmaf(r,  w1, a1);   a2  = fmaf(r,  w2, a2);
            a1n = fmaf(rn, w1, a1n);  a2n = fmaf(rn, w2, a2n);
        }
        sv1[tid] = a1; sv2[tid] = a2; sv1n[tid] = a1n; sv2n[tid] = a2n;
        __syncthreads();
        if (tid < 128) {
            int q = tid * 4;
            uint4 A, B;
            __half2 h;
            h = __floats2half2_rn(sv1[q],     sv1[q + 1]); A.x = *(uint32_t*)&h;
            h = __floats2half2_rn(sv1[q + 2], sv1[q + 3]); A.y = *(uint32_t*)&h;
            h = __floats2half2_rn(sv2[q],     sv2[q + 1]); A.z = *(uint32_t*)&h;
            h = __floats2half2_rn(sv2[q + 2], sv2[q + 3]); A.w = *(uint32_t*)&h;
            h = __floats2half2_rn(sv1n[q]     - sv1[q],     sv1n[q + 1] - sv1[q + 1]); B.x = *(uint32_t*)&h;
            h = __floats2half2_rn(sv1n[q + 2] - sv1[q + 2], sv1n[q + 3] - sv1[q + 3]); B.y = *(uint32_t*)&h;
            h = __floats2half2_rn(sv2n[q]     - sv2[q],     sv2n[q + 1] - sv2[q + 1]); B.z = *(uint32_t*)&h;
            h = __floats2half2_rn(sv2n[q + 2] - sv2[q + 2], sv2n[q + 3] - sv2[q + 3]); B.w = *(uint32_t*)&h;
            size_t o = (size_t)b * 128 + tid;
            g_TPa[o] = A;
            g_TPb[o] = B;
        }
        __syncthreads();
    }
}

// ================= prep 2: P = emb @ W_emb^T + b_in (FFMA2 GEMM) =========
#define PP_XSTRIDE 36
__device__ __forceinline__ void fma_block(ull (&acc)[4][4], const float* xr, const float* wr) {
    float4 xv = *(const float4*)xr;
    const ull* wp = (const ull*)wr;
    ull w0 = wp[0], w1 = wp[1], w2 = wp[2], w3 = wp[3];
    ull x0 = pack2(xv.x, xv.x), x1 = pack2(xv.y, xv.y);
    ull x2 = pack2(xv.z, xv.z), x3 = pack2(xv.w, xv.w);
    fma2(acc[0][0], w0, x0); fma2(acc[0][1], w1, x0);
    fma2(acc[0][2], w2, x0); fma2(acc[0][3], w3, x0);
    fma2(acc[1][0], w0, x1); fma2(acc[1][1], w1, x1);
    fma2(acc[1][2], w2, x1); fma2(acc[1][3], w3, x1);
    fma2(acc[2][0], w0, x2); fma2(acc[2][1], w1, x2);
    fma2(acc[2][2], w2, x2); fma2(acc[2][3], w3, x2);
    fma2(acc[3][0], w0, x3); fma2(acc[3][1], w1, x3);
    fma2(acc[3][2], w2, x3); fma2(acc[3][3], w3, x3);
}

#define PP_SMEM_BYTES (42496 * 4)
__global__ void __launch_bounds__(512, 1)
prep_P_kernel(const float* __restrict__ emb_table, const float* __restrict__ b_in) {
    extern __shared__ float sm[];
    float* Xs  = sm;
    float* WsA = sm + 9216;
    float* WsB = sm + 9216 + 16384;
    float* bsS = sm + 9216 + 32768;

    const int tid = threadIdx.x;
    const int p0  = blockIdx.x * 32;
    const int eg = tid & 7, jg = tid >> 3, jbase = jg * 8;
    const float4* emb4 = (const float4*)emb_table;

    for (int i = tid; i < 32 * 64; i += 512) {
        int e = i >> 6, c = i & 63;
        int pair = p0 + e;
        float4 v = (pair < NPAIR) ? emb4[(size_t)pair * 64 + c] : make_float4(0, 0, 0, 0);
        int kb = c * 4;
        Xs[(kb + 0) * PP_XSTRIDE + e] = v.x;
        Xs[(kb + 1) * PP_XSTRIDE + e] = v.y;
        Xs[(kb + 2) * PP_XSTRIDE + e] = v.z;
        Xs[(kb + 3) * PP_XSTRIDE + e] = v.w;
    }
    bsS[tid] = b_in[tid];

    {
        uint32_t sbase;
        asm("{ .reg .u64 t; cvta.to.shared.u64 t, %1; cvt.u32.u64 %0, t; }" : "=r"(sbase) : "l"(WsA));
        const float4* src = (const float4*)g_WT;
        for (int i = tid; i < 4096; i += 512) cp16(sbase + i * 16, src + i);
    }
    cp_commit();

    ull acc[4][4];
#pragma unroll
    for (int a = 0; a < 4; a++)
#pragma unroll
        for (int b = 0; b < 4; b++) acc[a][b] = 0ull;

    for (int t = 0; t < 8; ++t) {
        if (t + 1 < 8) {
            float* dstb = ((t + 1) & 1) ? WsB : WsA;
            uint32_t sbase;
            asm("{ .reg .u64 t; cvta.to.shared.u64 t, %1; cvt.u32.u64 %0, t; }" : "=r"(sbase) : "l"(dstb));
            const float4* src = (const float4*)(g_WT + (t + 1) * 32 * HID);
            for (int i = tid; i < 4096; i += 512) cp16(sbase + i * 16, src + i);
        }
        cp_commit();
        cp_wait1();
        __syncthreads();
        const float* W = (t & 1) ? WsB : WsA;
        const int kb = t * 32;
#pragma unroll
        for (int kk = 0; kk < 32; ++kk)
            fma_block(acc, Xs + (kb + kk) * PP_XSTRIDE + eg * 4, W + kk * HID + jbase);
        __syncthreads();
    }

#pragma unroll
    for (int e4 = 0; e4 < 4; ++e4) {
        int pair = p0 + eg * 4 + e4;
        if (pair < NPAIR) {
#pragma unroll
            for (int jp = 0; jp < 4; ++jp) {
                float2 v = unpack2(acc[e4][jp]);
                int j0 = jbase + jp * 2;
                g_PH[(size_t)pair * HID + j0]     = __float2half(v.x + bsS[j0]);
                g_PH[(size_t)pair * HID + j0 + 1] = __float2half(v.y + bsS[j0 + 1]);
            }
        }
    }
}

// ================= main kernel =================
#define MT          256
#define BEDG        64
#define WQS_F       4096                      // g_WQ as floats (1024 float4)
#define RB_F        (8 * 32 * 33)             // 8448
#define STG_F       (WQS_F + RB_F)            // 12544
#define MAIN_SMEM_B ((STG_F + 192) * 4)       // 50944 B

__global__ void __launch_bounds__(MT, 2)
pair_main(const int* __restrict__ anum,
          const int* __restrict__ edge_index,
          const int* __restrict__ edge_to_src,
          const float* __restrict__ dist,
          const float* __restrict__ b_out,
          float* __restrict__ out, int E) {
    extern __shared__ float sm[];
    float4* Wq4  = (float4*)sm;          // [jq][jpos][hpp][lane]
    float* Rb    = sm + WQS_F;
    int*   spidx = (int*)(sm + STG_F);
    int*   sbin  = (int*)(sm + STG_F + 64);
    float* sfrac = sm + STG_F + 128;

    const int tid  = threadIdx.x;
    const int wid  = tid >> 5;
    const int lane = tid & 31;
    const int e0   = blockIdx.x * BEDG;

    for (int i = tid; i < 1024; i += MT)
        Wq4[i] = g_WQ[i];
    if (tid < BEDG) {
        int e = e0 + tid; if (e >= E) e = E - 1;
        int f = edge_to_src[e];
        int i0 = edge_index[f];
        int i1 = edge_index[E + f];
        spidx[tid] = anum[i0] + NELEM * anum[i1];
        float x = dist[e] * ((float)NB / RBF_R);
        int b = (int)x; if (b > NB - 1) b = NB - 1;
        sbin[tid] = b;
        sfrac[tid] = x - (float)b;
    }
    __syncthreads();

    const uint2* P2 = (const uint2*)g_PH;
    float* RbW = Rb + wid * (32 * 33);
    float bo8 = __ldg(&b_out[lane & 7]);

#pragma unroll 1
    for (int grp = 0; grp < 2; ++grp) {
        int pe[4], be[4]; __half2 fh2[4];
#pragma unroll
        for (int e = 0; e < 4; ++e) {
            int sl = wid * 8 + grp * 4 + e;
            pe[e] = spidx[sl]; be[e] = sbin[sl];
            fh2[e] = __float2half2_rn(sfrac[sl]);
        }
        ull po2[4][4];                 // [edge][head-pair] f32x2 accumulators
#pragma unroll
        for (int a = 0; a < 4; a++)
#pragma unroll
            for (int b = 0; b < 4; b++) po2[a][b] = 0ull;

#pragma unroll
        for (int jq = 0; jq < 4; ++jq) {
            const int off = jq * 32 + lane;
            // ---- batched load front: 12 independent LDGs ----
            uint4 tA[4], tB[4]; uint2 ph[4];
#pragma unroll
            for (int e = 0; e < 4; ++e) {
                size_t tr = (size_t)be[e] * 128 + off;
                tA[e] = __ldg(g_TPa + tr);
                tB[e] = __ldg(g_TPb + tr);
                ph[e] = __ldg(P2 + (size_t)pe[e] * 128 + off);
            }
            // ---- compute hv splats per edge ----
            ull h[4][4];
#pragma unroll
            for (int e = 0; e < 4; ++e) {
                __half2 f2 = fh2[e];
                __half2 t1a = __hfma2(f2, *(const __half2*)&tB[e].x, *(const __half2*)&tA[e].x);
                __half2 t1b = __hfma2(f2, *(const __half2*)&tB[e].y, *(const __half2*)&tA[e].y);
                __half2 g2a = __hfma2(f2, *(const __half2*)&tB[e].z, *(const __half2*)&tA[e].z);
                __half2 g2b = __hfma2(f2, *(const __half2*)&tB[e].w, *(const __half2*)&tA[e].w);
                __half2 pa  = __hadd2(*(const __half2*)&ph[e].x, t1a);
                __half2 pb  = __hadd2(*(const __half2*)&ph[e].y, t1b);
                float2 p01 = __half22float2(pa);
                float2 p23 = __half22float2(pb);
                float2 g01 = __half22float2(g2a);
                float2 g23 = __half22float2(g2b);
                float q0 = 1.0f + __expf(-p01.x);
                float q1 = 1.0f + __expf(-p01.y);
                float q2 = 1.0f + __expf(-p23.x);
                float q3 = 1.0f + __expf(-p23.y);
                float q01 = q0 * q1, q23 = q2 * q3;
                float rall = rcpa(q01 * q23);
                float r01 = rall * q23, r23 = rall * q01;
                float hv0 = p01.x * g01.x * (r01 * q1);
                float hv1 = p01.y * g01.y * (r01 * q0);
                float hv2 = p23.x * g23.x * (r23 * q3);
                float hv3 = p23.y * g23.y * (r23 * q2);
                h[e][0] = pack2(hv0, hv0); h[e][1] = pack2(hv1, hv1);
                h[e][2] = pack2(hv2, hv2); h[e][3] = pack2(hv3, hv3);
            }
            // ---- head GEMM: conflict-free LDS.128, no packs ----
#pragma unroll
            for (int jpos = 0; jpos < 4; ++jpos) {
#pragma unroll
                for (int hpp = 0; hpp < 2; ++hpp) {
                    float4 wv = Wq4[((jq * 4 + jpos) * 2 + hpp) * 32 + lane];
                    ull w01 = ((const ull*)&wv)[0];
                    ull w23 = ((const ull*)&wv)[1];
#pragma unroll
                    for (int e = 0; e < 4; ++e) {
                        fma2(po2[e][2 * hpp],     w01, h[e][jpos]);
                        fma2(po2[e][2 * hpp + 1], w23, h[e][jpos]);
                    }
                }
            }
        }

        // per-warp smem reduction (conflict-free, deterministic)
#pragma unroll
        for (int e4 = 0; e4 < 4; ++e4)
#pragma unroll
            for (int hp = 0; hp < 4; ++hp) {
                float2 v = unpack2(po2[e4][hp]);
                RbW[lane * 33 + e4 * 8 + 2 * hp]     = v.x;
                RbW[lane * 33 + e4 * 8 + 2 * hp + 1] = v.y;
            }
        __syncwarp();
        float s = bo8;
#pragma unroll
        for (int l = 0; l < 32; ++l) s += RbW[l * 33 + lane];
        int e4 = lane >> 3, h = lane & 7;
        int ge = e0 + wid * 8 + grp * 4 + e4;
        if (ge < E) out[(size_t)h * E + ge] = s;
        __syncwarp();
    }
}

// ================= launch =================
extern "C" void kernel_launch(void* const* d_in, const int* in_sizes, int n_in,
                              void* d_out, int out_size) {
    const int*   anum        = (const int*)d_in[0];
    const int*   edge_index  = (const int*)d_in[1];
    const int*   edge_to_src = (const int*)d_in[2];
    const float* dist        = (const float*)d_in[3];
    const float* emb_table   = (const float*)d_in[4];
    const float* gate_W      = (const float*)d_in[5];
    const float* W_in        = (const float*)d_in[6];
    const float* b_in        = (const float*)d_in[7];
    const float* W_out       = (const float*)d_in[8];
    const float* b_out       = (const float*)d_in[9];
    float* out = (float*)d_out;
    const int E = in_sizes[2];

    {
        int tot = KEMB * HID + NG * HID * 2 + 1024;
        prep_transpose<<<(tot + 255) / 256, 256>>>(W_in, gate_W, W_out);
    }
    cudaFuncSetAttribute(prep_tables_pack, cudaFuncAttributeMaxDynamicSharedMemorySize, TBL_SMEM);
    prep_tables_pack<<<148, 512, TBL_SMEM>>>();
    cudaFuncSetAttribute(prep_P_kernel, cudaFuncAttributeMaxDynamicSharedMemorySize, PP_SMEM_BYTES);
    prep_P_kernel<<<(NPAIR + 31) / 32, 512, PP_SMEM_BYTES>>>(emb_table, b_in);
    cudaFuncSetAttribute(pair_main, cudaFuncAttributeMaxDynamicSharedMemorySize, MAIN_SMEM_B);
    pair_main<<<(E + BEDG - 1) / BEDG, MT, MAIN_SMEM_B>>>(
        anum, edge_index, edge_to_src, dist, b_out, out, E);
}

// round 9
// speedup vs baseline: 1.6562x; 1.1234x over previous
#include <cuda_runtime.h>
#include <cuda_bf16.h>
#include <cuda_fp16.h>
#include <mma.h>
#include <cstdint>

using namespace nvcuda;

#define NB        4096
#define HID       512
#define KEMB      256
#define NG        50
#define NELEM     100
#define NPAIR     (NELEM * NELEM)       // 10000
#define HEADS     8
#define RBF_R     12.0f

// ---------------- device scratch ----------------
__device__ __align__(16) __half         g_PH[(size_t)NPAIR * HID];     // fp16 (emb@W^T + b_in)
__device__ __align__(16) uint4          g_TPa[(size_t)NB * 128];       // values {v1h x4, v2h x4}
__device__ __align__(16) uint4          g_TPb[(size_t)NB * 128];       // slopes {s1h x4, s2h x4} (fp16)
__device__ __align__(16) float          g_WT[KEMB * HID];              // W_in emb part, [k][j]
__device__ __align__(16) float          g_Wr[NG * HID];                // W_in rbf part, [g][j]
__device__ __align__(16) float          g_Wg[NG * HID];                // gate_W,       [g][j]
// W_out interleaved: [jq][jpos][hpp][lane] float4
__device__ __align__(16) float4         g_WQ[1024];

typedef unsigned long long ull;

__device__ __forceinline__ void fma2(ull& d, ull a, ull b) {
    asm("fma.rn.f32x2 %0, %1, %2, %0;" : "+l"(d) : "l"(a), "l"(b));
}
__device__ __forceinline__ ull pack2(float x, float y) {
    ull r; asm("mov.b64 %0, {%1, %2};" : "=l"(r) : "f"(x), "f"(y)); return r;
}
__device__ __forceinline__ float2 unpack2(ull v) {
    float2 r; asm("mov.b64 {%0, %1}, %2;" : "=f"(r.x), "=f"(r.y) : "l"(v)); return r;
}
__device__ __forceinline__ float rcpa(float x) {
    float r; asm("rcp.approx.ftz.f32 %0, %1;" : "=f"(r) : "f"(x)); return r;
}

// ================= prep 0: transposes + W_out interleave =================
__global__ void prep_transpose(const float* __restrict__ W_in,
                               const float* __restrict__ gate_W,
                               const float* __restrict__ W_out) {
    int idx = blockIdx.x * blockDim.x + threadIdx.x;
    int total = KEMB * HID + NG * HID * 2 + 1024;
    if (idx >= total) return;
    if (idx < KEMB * HID) {
        int k = idx >> 9, j = idx & (HID - 1);
        g_WT[idx] = W_in[j * 306 + k];
    } else if (idx < KEMB * HID + NG * HID) {
        int r = idx - KEMB * HID;
        int g = r >> 9, j = r & (HID - 1);
        g_Wr[r] = W_in[j * 306 + 256 + g];
    } else if (idx < KEMB * HID + 2 * NG * HID) {
        int r = idx - KEMB * HID - NG * HID;
        int g = r >> 9, j = r & (HID - 1);
        g_Wg[r] = gate_W[j * NG + g];
    } else {
        int r = idx - KEMB * HID - 2 * NG * HID;   // [0, 1024)
        int lane = r & 31;
        int hpp  = (r >> 5) & 1;
        int jpos = (r >> 6) & 3;
        int jq   = r >> 8;
        int jj   = (jq * 32 + lane) * 4 + jpos;
        g_WQ[r] = make_float4(W_out[(4 * hpp + 0) * HID + jj],
                              W_out[(4 * hpp + 1) * HID + jj],
                              W_out[(4 * hpp + 2) * HID + jj],
                              W_out[(4 * hpp + 3) * HID + jj]);
    }
}

// ================= prep 1: rbf tables, packed SoA =================
#define TBL_SMEM ((2 * NG * HID + 4 * HID + 128) * 4)
__global__ void __launch_bounds__(512, 1) prep_tables_pack() {
    extern __shared__ float smw[];
    float* Ws1  = smw;
    float* Ws2  = smw + NG * HID;
    float* sv1  = smw + 2 * NG * HID;        // [512]
    float* sv2  = sv1 + HID;
    float* sv1n = sv2 + HID;
    float* sv2n = sv1n + HID;
    float* rbf  = sv2n + HID;                // [64]
    float* rbfn = rbf + 64;                  // [64]
    const int tid = threadIdx.x;
    for (int i = tid; i < NG * HID; i += 512) { Ws1[i] = g_Wr[i]; Ws2[i] = g_Wg[i]; }
    __syncthreads();
    const float delta = RBF_R / 49.0f;
    const float coeff = -0.5f / (delta * delta);
    const float binw  = RBF_R / (float)NB;
    for (int b = blockIdx.x; b < NB; b += gridDim.x) {
        if (tid < NG) {
            float t = (float)b * binw - (float)tid * delta;
            rbf[tid] = __expf(coeff * t * t);
        } else if (tid >= 64 && tid < 64 + NG) {
            float t = (float)(b + 1) * binw - (float)(tid - 64) * delta;
            rbfn[tid - 64] = __expf(coeff * t * t);
        }
        __syncthreads();
        float a1 = 0.f, a2 = 0.f, a1n = 0.f, a2n = 0.f;
#pragma unroll
        for (int g = 0; g < NG; ++g) {
            float r = rbf[g], rn = rbfn[g];
            float w1 = Ws1[g * HID + tid], w2 = Ws2[g * HID + tid];
            a1  = fmaf(r,  w1, a1);   a2  = fmaf(r,  w2, a2);
            a1n = fmaf(rn, w1, a1n);  a2n = fmaf(rn, w2, a2n);
        }
        sv1[tid] = a1; sv2[tid] = a2; sv1n[tid] = a1n; sv2n[tid] = a2n;
        __syncthreads();
        if (tid < 128) {
            int q = tid * 4;
            uint4 A, B;
            __half2 h;
            h = __floats2half2_rn(sv1[q],     sv1[q + 1]); A.x = *(uint32_t*)&h;
            h = __floats2half2_rn(sv1[q + 2], sv1[q + 3]); A.y = *(uint32_t*)&h;
            h = __floats2half2_rn(sv2[q],     sv2[q + 1]); A.z = *(uint32_t*)&h;
            h = __floats2half2_rn(sv2[q + 2], sv2[q + 3]); A.w = *(uint32_t*)&h;
            h = __floats2half2_rn(sv1n[q]     - sv1[q],     sv1n[q + 1] - sv1[q + 1]); B.x = *(uint32_t*)&h;
            h = __floats2half2_rn(sv1n[q + 2] - sv1[q + 2], sv1n[q + 3] - sv1[q + 3]); B.y = *(uint32_t*)&h;
            h = __floats2half2_rn(sv2n[q]     - sv2[q],     sv2n[q + 1] - sv2[q + 1]); B.z = *(uint32_t*)&h;
            h = __floats2half2_rn(sv2n[q + 2] - sv2[q + 2], sv2n[q + 3] - sv2[q + 3]); B.w = *(uint32_t*)&h;
            size_t o = (size_t)b * 128 + tid;
            g_TPa[o] = A;
            g_TPb[o] = B;
        }
        __syncthreads();
    }
}

// ================= prep 2: P = emb @ W_emb^T + b_in via WMMA bf16 split =========
// CTA tile: M=64, N=128. K staged in tiles of 32 (fp32 -> bf16 hi/lo in smem).
// 8 warps: warp_m = w>>2 (2 x 32 rows), warp_n = w&3 (4 x 32 cols); 2x2 acc frags.
#define PW_M   64
#define PW_N   128
#define PW_KT  32
#define A_LD   40      // bf16 elements per A row (padded)
#define B_LD   264     // bf16 elements per B row (padded)
#define EP_LD  132     // fp32 elements per epilogue row (padded)
#define PW_SMEM_BYTES (2 * (PW_M * A_LD * 2) + 2 * (PW_KT * B_LD * 2))   // 44032

__global__ void __launch_bounds__(256, 3)
prep_P_wmma(const float* __restrict__ emb_table, const float* __restrict__ b_in) {
    extern __shared__ char smraw[];
    __nv_bfloat16* Ah = (__nv_bfloat16*)smraw;                 // [64][A_LD]
    __nv_bfloat16* Al = Ah + PW_M * A_LD;
    __nv_bfloat16* Bh = Al + PW_M * A_LD;                      // [32][B_LD]
    __nv_bfloat16* Bl = Bh + PW_KT * B_LD;
    float* Ep = (float*)smraw;                                 // overlay [64][EP_LD]

    const int tid = threadIdx.x;
    const int w   = tid >> 5;
    const int p0  = blockIdx.x * PW_M;
    const int n0  = blockIdx.y * PW_N;
    const int wm  = w >> 2;     // 0..1
    const int wn  = w & 3;      // 0..3
    const float4* emb4 = (const float4*)emb_table;

    wmma::fragment<wmma::accumulator, 16, 16, 16, float> acc[2][2];
#pragma unroll
    for (int mi = 0; mi < 2; ++mi)
#pragma unroll
        for (int ni = 0; ni < 2; ++ni) wmma::fill_fragment(acc[mi][ni], 0.0f);

    for (int kt = 0; kt < KEMB; kt += PW_KT) {
        __syncthreads();
        // ---- stage A: 64 x 32 fp32 -> bf16 hi/lo ----
#pragma unroll
        for (int i = tid; i < 512; i += 256) {
            int r = i >> 3, cq = i & 7;
            int pair = p0 + r;
            float4 v = (pair < NPAIR) ? __ldg(emb4 + (size_t)pair * 64 + (kt >> 2) + cq)
                                      : make_float4(0, 0, 0, 0);
            __nv_bfloat162 h01 = __floats2bfloat162_rn(v.x, v.y);
            __nv_bfloat162 h23 = __floats2bfloat162_rn(v.z, v.w);
            __nv_bfloat162 l01 = __floats2bfloat162_rn(v.x - __low2float(h01), v.y - __high2float(h01));
            __nv_bfloat162 l23 = __floats2bfloat162_rn(v.z - __low2float(h23), v.w - __high2float(h23));
            uint2 hv; hv.x = *(uint32_t*)&h01; hv.y = *(uint32_t*)&h23;
            uint2 lv; lv.x = *(uint32_t*)&l01; lv.y = *(uint32_t*)&l23;
            *(uint2*)(Ah + r * A_LD + cq * 4) = hv;
            *(uint2*)(Al + r * A_LD + cq * 4) = lv;
        }
        // ---- stage B: 32 x 128 fp32 (g_WT[kt+r][n0+c]) -> bf16 hi/lo ----
#pragma unroll
        for (int i = tid; i < 1024; i += 256) {
            int r = i >> 5, cq = i & 31;
            float4 v = *(const float4*)&g_WT[(size_t)(kt + r) * HID + n0 + cq * 4];
            __nv_bfloat162 h01 = __floats2bfloat162_rn(v.x, v.y);
            __nv_bfloat162 h23 = __floats2bfloat162_rn(v.z, v.w);
            __nv_bfloat162 l01 = __floats2bfloat162_rn(v.x - __low2float(h01), v.y - __high2float(h01));
            __nv_bfloat162 l23 = __floats2bfloat162_rn(v.z - __low2float(h23), v.w - __high2float(h23));
            uint2 hv; hv.x = *(uint32_t*)&h01; hv.y = *(uint32_t*)&h23;
            uint2 lv; lv.x = *(uint32_t*)&l01; lv.y = *(uint32_t*)&l23;
            *(uint2*)(Bh + r * B_LD + cq * 4) = hv;
            *(uint2*)(Bl + r * B_LD + cq * 4) = lv;
        }
        __syncthreads();
        // ---- MMA: 2 k-steps of 16 ----
#pragma unroll
        for (int kk = 0; kk < 2; ++kk) {
            wmma::fragment<wmma::matrix_a, 16, 16, 16, __nv_bfloat16, wmma::row_major> ah[2], al[2];
            wmma::fragment<wmma::matrix_b, 16, 16, 16, __nv_bfloat16, wmma::row_major> bh[2], bl[2];
#pragma unroll
            for (int mi = 0; mi < 2; ++mi) {
                const __nv_bfloat16* ap = Ah + (wm * 32 + mi * 16) * A_LD + kk * 16;
                const __nv_bfloat16* lp = Al + (wm * 32 + mi * 16) * A_LD + kk * 16;
                wmma::load_matrix_sync(ah[mi], ap, A_LD);
                wmma::load_matrix_sync(al[mi], lp, A_LD);
            }
#pragma unroll
            for (int ni = 0; ni < 2; ++ni) {
                const __nv_bfloat16* bp = Bh + (kk * 16) * B_LD + wn * 32 + ni * 16;
                const __nv_bfloat16* lp = Bl + (kk * 16) * B_LD + wn * 32 + ni * 16;
                wmma::load_matrix_sync(bh[ni], bp, B_LD);
                wmma::load_matrix_sync(bl[ni], lp, B_LD);
            }
#pragma unroll
            for (int mi = 0; mi < 2; ++mi)
#pragma unroll
                for (int ni = 0; ni < 2; ++ni) {
                    wmma::mma_sync(acc[mi][ni], ah[mi], bh[ni], acc[mi][ni]);
                    wmma::mma_sync(acc[mi][ni], ah[mi], bl[ni], acc[mi][ni]);
                    wmma::mma_sync(acc[mi][ni], al[mi], bh[ni], acc[mi][ni]);
                }
        }
    }
    __syncthreads();   // stage buffers dead; overlay epilogue
#pragma unroll
    for (int mi = 0; mi < 2; ++mi)
#pragma unroll
        for (int ni = 0; ni < 2; ++ni)
            wmma::store_matrix_sync(Ep + (wm * 32 + mi * 16) * EP_LD + wn * 32 + ni * 16,
                                    acc[mi][ni], EP_LD, wmma::mem_row_major);
    __syncthreads();
#pragma unroll
    for (int i = tid; i < PW_M * PW_N; i += 256) {
        int r = i >> 7, c = i & 127;
        int pair = p0 + r;
        if (pair < NPAIR)
            g_PH[(size_t)pair * HID + n0 + c] =
                __float2half(Ep[r * EP_LD + c] + __ldg(&b_in[n0 + c]));
    }
}

// ================= main kernel (R8, unchanged) =================
#define MT          256
#define BEDG        64
#define WQS_F       4096                      // g_WQ as floats (1024 float4)
#define RB_F        (8 * 32 * 33)             // 8448
#define STG_F       (WQS_F + RB_F)            // 12544
#define MAIN_SMEM_B ((STG_F + 192) * 4)       // 50944 B

__global__ void __launch_bounds__(MT, 2)
pair_main(const int* __restrict__ anum,
          const int* __restrict__ edge_index,
          const int* __restrict__ edge_to_src,
          const float* __restrict__ dist,
          const float* __restrict__ b_out,
          float* __restrict__ out, int E) {
    extern __shared__ float sm[];
    float4* Wq4  = (float4*)sm;          // [jq][jpos][hpp][lane]
    float* Rb    = sm + WQS_F;
    int*   spidx = (int*)(sm + STG_F);
    int*   sbin  = (int*)(sm + STG_F + 64);
    float* sfrac = sm + STG_F + 128;

    const int tid  = threadIdx.x;
    const int wid  = tid >> 5;
    const int lane = tid & 31;
    const int e0   = blockIdx.x * BEDG;

    for (int i = tid; i < 1024; i += MT)
        Wq4[i] = g_WQ[i];
    if (tid < BEDG) {
        int e = e0 + tid; if (e >= E) e = E - 1;
        int f = edge_to_src[e];
        int i0 = edge_index[f];
        int i1 = edge_index[E + f];
        spidx[tid] = anum[i0] + NELEM * anum[i1];
        float x = dist[e] * ((float)NB / RBF_R);
        int b = (int)x; if (b > NB - 1) b = NB - 1;
        sbin[tid] = b;
        sfrac[tid] = x - (float)b;
    }
    __syncthreads();

    const uint2* P2 = (const uint2*)g_PH;
    float* RbW = Rb + wid * (32 * 33);
    float bo8 = __ldg(&b_out[lane & 7]);

#pragma unroll 1
    for (int grp = 0; grp < 2; ++grp) {
        int pe[4], be[4]; __half2 fh2[4];
#pragma unroll
        for (int e = 0; e < 4; ++e) {
            int sl = wid * 8 + grp * 4 + e;
            pe[e] = spidx[sl]; be[e] = sbin[sl];
            fh2[e] = __float2half2_rn(sfrac[sl]);
        }
        ull po2[4][4];
#pragma unroll
        for (int a = 0; a < 4; a++)
#pragma unroll
            for (int b = 0; b < 4; b++) po2[a][b] = 0ull;

#pragma unroll
        for (int jq = 0; jq < 4; ++jq) {
            const int off = jq * 32 + lane;
            uint4 tA[4], tB[4]; uint2 ph[4];
#pragma unroll
            for (int e = 0; e < 4; ++e) {
                size_t tr = (size_t)be[e] * 128 + off;
                tA[e] = __ldg(g_TPa + tr);
                tB[e] = __ldg(g_TPb + tr);
                ph[e] = __ldg(P2 + (size_t)pe[e] * 128 + off);
            }
            ull h[4][4];
#pragma unroll
            for (int e = 0; e < 4; ++e) {
                __half2 f2 = fh2[e];
                __half2 t1a = __hfma2(f2, *(const __half2*)&tB[e].x, *(const __half2*)&tA[e].x);
                __half2 t1b = __hfma2(f2, *(const __half2*)&tB[e].y, *(const __half2*)&tA[e].y);
                __half2 g2a = __hfma2(f2, *(const __half2*)&tB[e].z, *(const __half2*)&tA[e].z);
                __half2 g2b = __hfma2(f2, *(const __half2*)&tB[e].w, *(const __half2*)&tA[e].w);
                __half2 pa  = __hadd2(*(const __half2*)&ph[e].x, t1a);
                __half2 pb  = __hadd2(*(const __half2*)&ph[e].y, t1b);
                float2 p01 = __half22float2(pa);
                float2 p23 = __half22float2(pb);
                float2 g01 = __half22float2(g2a);
                float2 g23 = __half22float2(g2b);
                float q0 = 1.0f + __expf(-p01.x);
                float q1 = 1.0f + __expf(-p01.y);
                float q2 = 1.0f + __expf(-p23.x);
                float q3 = 1.0f + __expf(-p23.y);
                float q01 = q0 * q1, q23 = q2 * q3;
                float rall = rcpa(q01 * q23);
                float r01 = rall * q23, r23 = rall * q01;
                float hv0 = p01.x * g01.x * (r01 * q1);
                float hv1 = p01.y * g01.y * (r01 * q0);
                float hv2 = p23.x * g23.x * (r23 * q3);
                float hv3 = p23.y * g23.y * (r23 * q2);
                h[e][0] = pack2(hv0, hv0); h[e][1] = pack2(hv1, hv1);
                h[e][2] = pack2(hv2, hv2); h[e][3] = pack2(hv3, hv3);
            }
#pragma unroll
            for (int jpos = 0; jpos < 4; ++jpos) {
#pragma unroll
                for (int hpp = 0; hpp < 2; ++hpp) {
                    float4 wv = Wq4[((jq * 4 + jpos) * 2 + hpp) * 32 + lane];
                    ull w01 = ((const ull*)&wv)[0];
                    ull w23 = ((const ull*)&wv)[1];
#pragma unroll
                    for (int e = 0; e < 4; ++e) {
                        fma2(po2[e][2 * hpp],     w01, h[e][jpos]);
                        fma2(po2[e][2 * hpp + 1], w23, h[e][jpos]);
                    }
                }
            }
        }

#pragma unroll
        for (int e4 = 0; e4 < 4; ++e4)
#pragma unroll
            for (int hp = 0; hp < 4; ++hp) {
                float2 v = unpack2(po2[e4][hp]);
                RbW[lane * 33 + e4 * 8 + 2 * hp]     = v.x;
                RbW[lane * 33 + e4 * 8 + 2 * hp + 1] = v.y;
            }
        __syncwarp();
        float s = bo8;
#pragma unroll
        for (int l = 0; l < 32; ++l) s += RbW[l * 33 + lane];
        int e4 = lane >> 3, h = lane & 7;
        int ge = e0 + wid * 8 + grp * 4 + e4;
        if (ge < E) out[(size_t)h * E + ge] = s;
        __syncwarp();
    }
}

// ================= launch =================
extern "C" void kernel_launch(void* const* d_in, const int* in_sizes, int n_in,
                              void* d_out, int out_size) {
    const int*   anum        = (const int*)d_in[0];
    const int*   edge_index  = (const int*)d_in[1];
    const int*   edge_to_src = (const int*)d_in[2];
    const float* dist        = (const float*)d_in[3];
    const float* emb_table   = (const float*)d_in[4];
    const float* gate_W      = (const float*)d_in[5];
    const float* W_in        = (const float*)d_in[6];
    const float* b_in        = (const float*)d_in[7];
    const float* W_out       = (const float*)d_in[8];
    const float* b_out       = (const float*)d_in[9];
    float* out = (float*)d_out;
    const int E = in_sizes[2];

    {
        int tot = KEMB * HID + NG * HID * 2 + 1024;
        prep_transpose<<<(tot + 255) / 256, 256>>>(W_in, gate_W, W_out);
    }
    cudaFuncSetAttribute(prep_tables_pack, cudaFuncAttributeMaxDynamicSharedMemorySize, TBL_SMEM);
    prep_tables_pack<<<148, 512, TBL_SMEM>>>();
    {
        dim3 grid((NPAIR + PW_M - 1) / PW_M, HID / PW_N);   // 157 x 4
        cudaFuncSetAttribute(prep_P_wmma, cudaFuncAttributeMaxDynamicSharedMemorySize, PW_SMEM_BYTES);
        prep_P_wmma<<<grid, 256, PW_SMEM_BYTES>>>(emb_table, b_in);
    }
    cudaFuncSetAttribute(pair_main, cudaFuncAttributeMaxDynamicSharedMemorySize, MAIN_SMEM_B);
    pair_main<<<(E + BEDG - 1) / BEDG, MT, MAIN_SMEM_B>>>(
        anum, edge_index, edge_to_src, dist, b_out, out, E);
}